// round 13
// baseline (speedup 1.0000x reference)
#include <cuda_runtime.h>
#include <cuda_fp16.h>
#include <cstdint>

#define N_C 8192
#define N_E 8192
#define IN_F 256
#define D 128
#define SCALE 0.08838834764831845f  /* 1/sqrt(128) */

#define BM 64            /* rows per block (attn) */
#define BN 128           /* cols per tile (attn) */
#define NT (N_E / BN)    /* 64 tiles */
#define LDH 136          /* attn smem leading dim in halves */
#define LDB (LDH * 2)    /* bytes: 272 */
#define NTHR 512         /* 16 warps */

// -------- device scratch (static: no allocation allowed) --------
__device__ __half gQh[N_C * D];              // pre-scaled
__device__ __half gKh[N_E * D];              // row-major [key][d]
__device__ __half gVt[D * N_E];              // TRANSPOSED [d][key]
__device__ __half gPstage[(size_t)N_C * N_E]; // fp16 unnormalized attn staging
__device__ float  gOscratch[N_C * D];

// smem byte offsets for attn kernel (209408 B total)
#define QOFF   0
#define KOFF0  17408
#define KOFF1  (KOFF0 + 34816)
#define VOFF0  (KOFF1 + 34816)
#define VOFF1  (VOFF0 + 34816)
#define VOFF2  (VOFF1 + 34816)
#define POFF   (VOFF2 + 34816)
#define ROWOFF (POFF + 17408)
#define INVOFF (ROWOFF + 256)
#define SMEM_TOTAL (INVOFF + 256)

// -------- helpers --------
__device__ __forceinline__ uint32_t smem_u32(const void* p) {
    uint32_t a;
    asm("{ .reg .u64 t; cvta.to.shared.u64 t, %1; cvt.u32.u64 %0, t; }" : "=r"(a) : "l"(p));
    return a;
}
__device__ __forceinline__ void cpa16(uint32_t dst, const void* src) {
    asm volatile("cp.async.cg.shared.global [%0], [%1], 16;\n" :: "r"(dst), "l"(src));
}
#define CP_COMMIT() asm volatile("cp.async.commit_group;\n")
#define CP_WAIT1()  asm volatile("cp.async.wait_group 1;\n")

__device__ __forceinline__ void mma16(float* c,
                                      uint32_t a0, uint32_t a1, uint32_t a2, uint32_t a3,
                                      uint32_t b0, uint32_t b1) {
    asm volatile(
        "mma.sync.aligned.m16n8k16.row.col.f32.f16.f16.f32 "
        "{%0,%1,%2,%3}, {%4,%5,%6,%7}, {%8,%9}, {%0,%1,%2,%3};"
        : "+f"(c[0]), "+f"(c[1]), "+f"(c[2]), "+f"(c[3])
        : "r"(a0), "r"(a1), "r"(a2), "r"(a3), "r"(b0), "r"(b1));
}

// ==================== K1: fused projections via fp16 mma ====================
#define LDA1 72
__global__ __launch_bounds__(128) void proj_kernel(
    const float* __restrict__ embC, const float* __restrict__ embE,
    const float* __restrict__ Wq, const float* __restrict__ bq,
    const float* __restrict__ Wk, const float* __restrict__ bk,
    const float* __restrict__ Wv, const float* __restrict__ bv)
{
    int which = blockIdx.y;
    const float* src = (which == 0) ? embC : embE;
    const float* W   = (which == 0) ? Wq : (which == 1) ? Wk : Wv;
    const float* b   = (which == 0) ? bq : (which == 1) ? bk : bv;
    float oscale     = (which == 0) ? SCALE : 1.0f;

    __shared__ __half sA[64 * LDA1];
    __shared__ __half sBt[128 * LDA1];
    __shared__ __half sVs[128 * LDA1];

    int tid = threadIdx.x, lane = tid & 31, wid = tid >> 5;
    int g = lane >> 2, tig = lane & 3;
    int r0 = blockIdx.x * 64;
    int wr0 = wid * 16;

    float acc[16][4];
#pragma unroll
    for (int nf = 0; nf < 16; nf++)
#pragma unroll
        for (int c = 0; c < 4; c++) acc[nf][c] = 0.f;

    for (int ch = 0; ch < 4; ch++) {
        int k0 = ch * 64;
        __syncthreads();
#pragma unroll
        for (int i = 0; i < 8; i++) {
            int idx = tid + i * 128;
            int row = idx >> 4, c4 = (idx & 15) << 2;
            float4 v = *(const float4*)&src[(size_t)(r0 + row) * IN_F + k0 + c4];
            __half tmp[4] = { __float2half(v.x), __float2half(v.y),
                              __float2half(v.z), __float2half(v.w) };
            *(uint2*)&sA[row * LDA1 + c4] = *(const uint2*)tmp;
        }
#pragma unroll
        for (int i = 0; i < 16; i++) {
            int idx = tid + i * 128;
            int k = idx >> 5, n4 = (idx & 31) << 2;
            float4 v = *(const float4*)&W[(size_t)(k0 + k) * D + n4];
            sBt[(n4 + 0) * LDA1 + k] = __float2half(v.x);
            sBt[(n4 + 1) * LDA1 + k] = __float2half(v.y);
            sBt[(n4 + 2) * LDA1 + k] = __float2half(v.z);
            sBt[(n4 + 3) * LDA1 + k] = __float2half(v.w);
        }
        __syncthreads();
#pragma unroll
        for (int ks = 0; ks < 4; ks++) {
            int kb = ks * 16 + 2 * tig;
            uint32_t a0 = *(const uint32_t*)&sA[(wr0 + g) * LDA1 + kb];
            uint32_t a1 = *(const uint32_t*)&sA[(wr0 + 8 + g) * LDA1 + kb];
            uint32_t a2 = *(const uint32_t*)&sA[(wr0 + g) * LDA1 + kb + 8];
            uint32_t a3 = *(const uint32_t*)&sA[(wr0 + 8 + g) * LDA1 + kb + 8];
#pragma unroll
            for (int nf = 0; nf < 16; nf++) {
                uint32_t b0 = *(const uint32_t*)&sBt[(nf * 8 + g) * LDA1 + kb];
                uint32_t b1 = *(const uint32_t*)&sBt[(nf * 8 + g) * LDA1 + kb + 8];
                mma16(acc[nf], a0, a1, a2, a3, b0, b1);
            }
        }
    }

    if (which == 2) {
#pragma unroll
        for (int nf = 0; nf < 16; nf++) {
            int col = nf * 8 + 2 * tig;
            float2 bb = *(const float2*)&b[col];
            sVs[(col + 0) * LDA1 + wr0 + g]     = __float2half(acc[nf][0] + bb.x);
            sVs[(col + 1) * LDA1 + wr0 + g]     = __float2half(acc[nf][1] + bb.y);
            sVs[(col + 0) * LDA1 + wr0 + 8 + g] = __float2half(acc[nf][2] + bb.x);
            sVs[(col + 1) * LDA1 + wr0 + 8 + g] = __float2half(acc[nf][3] + bb.y);
        }
        __syncthreads();
#pragma unroll
        for (int i = 0; i < 8; i++) {
            int idx = tid + i * 128;
            int d = idx >> 3, k8 = idx & 7;
            uint4 v = *(const uint4*)&sVs[d * LDA1 + k8 * 8];
            *(uint4*)&gVt[(size_t)d * N_E + r0 + k8 * 8] = v;
        }
    } else {
        __half* dst = (which == 0) ? gQh : gKh;
#pragma unroll
        for (int nf = 0; nf < 16; nf++) {
            int col = nf * 8 + 2 * tig;
            float2 bb = *(const float2*)&b[col];
            __half2 h0 = __floats2half2_rn((acc[nf][0] + bb.x) * oscale,
                                           (acc[nf][1] + bb.y) * oscale);
            __half2 h1 = __floats2half2_rn((acc[nf][2] + bb.x) * oscale,
                                           (acc[nf][3] + bb.y) * oscale);
            *(uint32_t*)&dst[(size_t)(r0 + wr0 + g) * D + col]     = *(uint32_t*)&h0;
            *(uint32_t*)&dst[(size_t)(r0 + wr0 + 8 + g) * D + col] = *(uint32_t*)&h1;
        }
    }
}

// ==================== K2: attention (2 barriers/tile, V triple-buffer) =======
// 128 blocks x 64 rows, 512 threads = 16 warps as 4(m) x 4(n); warp tile 16x32.
__global__ __launch_bounds__(NTHR, 1) void attn_kernel(
    const int* __restrict__ mask, float* __restrict__ attn, float* __restrict__ out0)
{
    if (out0 == nullptr) out0 = gOscratch;

    extern __shared__ char sm[];
    uint32_t sb = smem_u32(sm);
    float* sRow = (float*)(sm + ROWOFF);
    float* sInv = (float*)(sm + INVOFF);

    int tid  = threadIdx.x;
    int lane = tid & 31, wid = tid >> 5;
    int g = lane >> 2, tig = lane & 3;
    int wm = wid >> 2, wn = wid & 3;       // 4 m-groups x 4 n-groups
    int i0 = blockIdx.x * BM;

    if (tid < 64) sRow[tid] = 0.f;

    int mrow = wm * 16 + g;                // local row (partner row adds 8)
    int ncol0 = wn * 32;                   // S-phase col base / PV-phase d base

    // ---- Q tile (64 x 128 halves) ----
#pragma unroll
    for (int k = 0; k < 2; k++) {
        int t = tid + k * NTHR;
        int r = t >> 4, cc = t & 15;
        uint4 v = *(const uint4*)&gQh[(size_t)(i0 + r) * D + cc * 8];
        *(uint4*)(sm + QOFF + r * LDB + cc * 16) = v;
    }

    const uint32_t kbuf[2] = { sb + KOFF0, sb + KOFF1 };
    const uint32_t vbuf[3] = { sb + VOFF0, sb + VOFF1, sb + VOFF2 };
#pragma unroll
    for (int k = 0; k < 4; k++) {
        int c = tid + k * NTHR;
        int row = c >> 4, cc = c & 15;
        cpa16(kbuf[0] + row * LDB + cc * 16, &gKh[(size_t)row * D + cc * 8]);
        cpa16(vbuf[0] + row * LDB + cc * 16, &gVt[(size_t)row * N_E + cc * 8]);
    }
    CP_COMMIT();
#pragma unroll
    for (int k = 0; k < 4; k++) {
        int c = tid + k * NTHR;
        int row = c >> 4, cc = c & 15;
        cpa16(kbuf[1] + row * LDB + cc * 16, &gKh[(size_t)(BN + row) * D + cc * 8]);
        cpa16(vbuf[1] + row * LDB + cc * 16, &gVt[(size_t)row * N_E + BN + cc * 8]);
    }
    CP_COMMIT();

    float oAcc[4][4];                      // 16 rows x 32 d
#pragma unroll
    for (int ni = 0; ni < 4; ni++)
#pragma unroll
        for (int c = 0; c < 4; c++) oAcc[ni][c] = 0.f;
    float rs0 = 0.f, rs1 = 0.f;

    int vcur = 0;                          // jt % 3
    int vpre = 2;                          // (jt + 2) % 3

    for (int jt = 0; jt < NT; jt++) {
        int j0 = jt * BN;
        uint32_t sK = kbuf[jt & 1], sV = vbuf[vcur];

        CP_WAIT1();
        __syncthreads();                   // tile jt resident; PV(jt-1) done everywhere

        // ---- V prefetch for jt+2 (buffer free since barrier above) ----
        if (jt + 2 < NT) {
            int jn = (jt + 2) * BN;
            uint32_t vb2 = vbuf[vpre];
#pragma unroll
            for (int k = 0; k < 4; k++) {
                int c = tid + k * NTHR;
                int row = c >> 4, cc = c & 15;
                cpa16(vb2 + row * LDB + cc * 16, &gVt[(size_t)row * N_E + jn + cc * 8]);
            }
        }

        // ---- mask prefetch (hidden under S mma) ----
        int2 mreg[4][2];
#pragma unroll
        for (int ni = 0; ni < 4; ni++) {
            size_t gr0 = (size_t)(i0 + mrow) * N_E + j0 + ncol0 + ni * 8 + 2 * tig;
            mreg[ni][0] = *(const int2*)&mask[gr0];
            mreg[ni][1] = *(const int2*)&mask[gr0 + 8 * N_E];
        }

        // ---- S = Q @ K^T  (k = 128) ----
        float sAcc[4][4];
#pragma unroll
        for (int ni = 0; ni < 4; ni++)
#pragma unroll
            for (int c = 0; c < 4; c++) sAcc[ni][c] = 0.f;

#pragma unroll
        for (int ks = 0; ks < 8; ks++) {
            int kb = (ks * 16 + 2 * tig) * 2;
            uint32_t ro = (uint32_t)mrow * LDB;
            uint32_t a0 = *(const uint32_t*)(sm + QOFF + ro + kb);
            uint32_t a1 = *(const uint32_t*)(sm + QOFF + ro + 8 * LDB + kb);
            uint32_t a2 = *(const uint32_t*)(sm + QOFF + ro + kb + 16);
            uint32_t a3 = *(const uint32_t*)(sm + QOFF + ro + 8 * LDB + kb + 16);
#pragma unroll
            for (int ni = 0; ni < 4; ni++) {
                uint32_t rb = (uint32_t)(ncol0 + ni * 8 + g) * LDB;
                uint32_t b0 = *(const uint32_t*)((char*)sm + (sK - sb) + rb + kb);
                uint32_t b1 = *(const uint32_t*)((char*)sm + (sK - sb) + rb + kb + 16);
                mma16(sAcc[ni], a0, a1, a2, a3, b0, b1);
            }
        }

        // ---- epilogue: mask + exp, fill sP, rowsum ----
#pragma unroll
        for (int ni = 0; ni < 4; ni++) {
            int lc = ncol0 + ni * 8 + 2 * tig;
            float p0 = mreg[ni][0].x ? __expf(sAcc[ni][0]) : 0.f;
            float p1 = mreg[ni][0].y ? __expf(sAcc[ni][1]) : 0.f;
            float p2 = mreg[ni][1].x ? __expf(sAcc[ni][2]) : 0.f;
            float p3 = mreg[ni][1].y ? __expf(sAcc[ni][3]) : 0.f;
            rs0 += p0 + p1;
            rs1 += p2 + p3;
            __half2 h0 = __floats2half2_rn(p0, p1);
            __half2 h1 = __floats2half2_rn(p2, p3);
            *(uint32_t*)(sm + POFF + mrow * LDB + lc * 2)       = *(uint32_t*)&h0;
            *(uint32_t*)(sm + POFF + (mrow + 8) * LDB + lc * 2) = *(uint32_t*)&h1;
        }
        __syncthreads();                   // sP complete; K(jt) reads all done

        // ---- K prefetch for jt+2 (K buffer jt&1 is free now) ----
        if (jt + 2 < NT) {
            int jn = (jt + 2) * BN;
            uint32_t kb2 = kbuf[jt & 1];
#pragma unroll
            for (int k = 0; k < 4; k++) {
                int c = tid + k * NTHR;
                int row = c >> 4, cc = c & 15;
                cpa16(kb2 + row * LDB + cc * 16, &gKh[(size_t)(jn + row) * D + cc * 8]);
            }
        }

        // ---- coalesced sP -> gPstage copy (full 32B sectors) ----
#pragma unroll
        for (int k = 0; k < 2; k++) {
            int t = tid + k * NTHR;
            int r = t >> 4, cc = t & 15;
            uint4 v = *(const uint4*)(sm + POFF + r * LDB + cc * 16);
            *(uint4*)&gPstage[(size_t)(i0 + r) * N_E + j0 + cc * 8] = v;
        }

        // ---- O += P @ V  (k = 128 keys, warp covers 32 d) ----
#pragma unroll
        for (int ks = 0; ks < 8; ks++) {
            int kb = (ks * 16 + 2 * tig) * 2;
            uint32_t ro = (uint32_t)mrow * LDB;
            uint32_t a0 = *(const uint32_t*)(sm + POFF + ro + kb);
            uint32_t a1 = *(const uint32_t*)(sm + POFF + ro + 8 * LDB + kb);
            uint32_t a2 = *(const uint32_t*)(sm + POFF + ro + kb + 16);
            uint32_t a3 = *(const uint32_t*)(sm + POFF + ro + 8 * LDB + kb + 16);
#pragma unroll
            for (int ni = 0; ni < 4; ni++) {
                uint32_t rb = (uint32_t)(ncol0 + ni * 8 + g) * LDB;  // d row
                uint32_t b0 = *(const uint32_t*)((char*)sm + (sV - sb) + rb + kb);
                uint32_t b1 = *(const uint32_t*)((char*)sm + (sV - sb) + rb + kb + 16);
                mma16(oAcc[ni], a0, a1, a2, a3, b0, b1);
            }
        }
        CP_COMMIT();                       // one group/iter = {V(jt+2), K(jt+2)}

        vcur = (vcur == 2) ? 0 : vcur + 1;
        vpre = (vpre == 2) ? 0 : vpre + 1;
    }

    // ---- rowsum reduce -> inv (4 n-warps contribute per row) ----
    {
        float v0 = rs0, v1 = rs1;
        v0 += __shfl_xor_sync(0xffffffffu, v0, 1);
        v0 += __shfl_xor_sync(0xffffffffu, v0, 2);
        v1 += __shfl_xor_sync(0xffffffffu, v1, 1);
        v1 += __shfl_xor_sync(0xffffffffu, v1, 2);
        if (tig == 0) {
            atomicAdd(&sRow[wm * 16 + g], v0);
            atomicAdd(&sRow[wm * 16 + 8 + g], v1);
        }
    }
    __syncthreads();
    if (tid < 64) sInv[tid] = 1.0f / sRow[tid];
    __syncthreads();

    // ---- write normalized O (warp owns rows wm*16.., d cols wn*32..) ----
    {
        float iv0 = sInv[mrow], iv1 = sInv[mrow + 8];
#pragma unroll
        for (int ni = 0; ni < 4; ni++) {
            int c = ncol0 + ni * 8 + 2 * tig;
            *(float2*)&out0[(size_t)(i0 + mrow) * D + c] =
                make_float2(oAcc[ni][0] * iv0, oAcc[ni][1] * iv0);
            *(float2*)&out0[(size_t)(i0 + mrow + 8) * D + c] =
                make_float2(oAcc[ni][2] * iv1, oAcc[ni][3] * iv1);
        }
    }

    // ---- fused normalization: fp16 stage -> fp32 attn, fully coalesced ----
    const __half* pst = gPstage + (size_t)i0 * N_E;
    float4* a4 = (float4*)(attn + (size_t)i0 * N_E);
    const int totalc = 64 * (N_E / 4);     // 131072 uint2 chunks = 512*8*32
    for (int base = 0; base < totalc; base += NTHR * 8) {
        uint2 v[8];
        int idx[8];
#pragma unroll
        for (int u = 0; u < 8; u++) {
            idx[u] = base + u * NTHR + tid;
            v[u] = *(const uint2*)&pst[(size_t)idx[u] * 4];
        }
#pragma unroll
        for (int u = 0; u < 8; u++) {
            float inv = sInv[idx[u] >> 11];    // 2048 uint2 per row
            const __half2* h2 = (const __half2*)&v[u];
            float2 f0 = __half22float2(h2[0]);
            float2 f1 = __half22float2(h2[1]);
            a4[idx[u]] = make_float4(f0.x * inv, f0.y * inv, f1.x * inv, f1.y * inv);
        }
    }
}

// ==================== host ====================
extern "C" void kernel_launch(void* const* d_in, const int* in_sizes, int n_in,
                              void* d_out, int out_size)
{
    const float* embC = (const float*)d_in[0];
    const float* embE = (const float*)d_in[1];
    const int*   mask = (const int*)d_in[2];
    const float* Wq = (const float*)d_in[3];
    const float* bq = (const float*)d_in[4];
    const float* Wk = (const float*)d_in[5];
    const float* bk = (const float*)d_in[6];
    const float* Wv = (const float*)d_in[7];
    const float* bv = (const float*)d_in[8];

    float* base = (float*)d_out;
    long long t2 = (long long)N_C * N_E;

    float* out0;
    float* attn;
    if ((long long)out_size == t2) {
        out0 = nullptr;
        attn = base;
    } else {
        out0 = base;
        attn = base + (long long)N_C * D;
    }

    dim3 pgrid(N_C / 64, 3);
    proj_kernel<<<pgrid, 128>>>(embC, embE, Wq, bq, Wk, bk, Wv, bv);

    static int configured = 0;
    if (!configured) {
        cudaFuncSetAttribute(attn_kernel, cudaFuncAttributeMaxDynamicSharedMemorySize, SMEM_TOTAL);
        configured = 1;
    }
    attn_kernel<<<N_C / BM, NTHR, SMEM_TOTAL>>>(mask, attn, out0);
}

// round 14
// speedup vs baseline: 1.0001x; 1.0001x over previous
#include <cuda_runtime.h>
#include <cuda_fp16.h>
#include <cstdint>

#define N_C 8192
#define N_E 8192
#define IN_F 256
#define D 128
#define SCALE 0.08838834764831845f  /* 1/sqrt(128) */

#define BM 64            /* rows per block (attn) */
#define BN 128           /* cols per tile (attn) */
#define NT (N_E / BN)    /* 64 tiles */
#define LDH 136          /* attn smem leading dim in halves */
#define LDB (LDH * 2)    /* bytes: 272 */
#define NTHR 512         /* 16 warps */

// -------- device scratch (static: no allocation allowed) --------
__device__ __half gQh[N_C * D];              // pre-scaled
__device__ __half gKh[N_E * D];              // row-major [key][d]
__device__ __half gVt[D * N_E];              // TRANSPOSED [d][key]
__device__ __half gPstage[(size_t)N_C * N_E]; // fp16 unnormalized attn staging
__device__ float  gOscratch[N_C * D];

// smem byte offsets for attn kernel (R12 layout: 174.6 KB -> ~53 KB L1D left)
#define QOFF   0
#define KOFF0  17408
#define KOFF1  (17408 + 34816)
#define VOFF0  (17408 + 69632)
#define VOFF1  (17408 + 69632 + 34816)
#define POFF   (17408 + 139264)
#define ROWOFF (POFF + 17408)
#define INVOFF (ROWOFF + 256)
#define SMEM_TOTAL (INVOFF + 256)

// -------- helpers --------
__device__ __forceinline__ uint32_t smem_u32(const void* p) {
    uint32_t a;
    asm("{ .reg .u64 t; cvta.to.shared.u64 t, %1; cvt.u32.u64 %0, t; }" : "=r"(a) : "l"(p));
    return a;
}
__device__ __forceinline__ void cpa16(uint32_t dst, const void* src) {
    asm volatile("cp.async.cg.shared.global [%0], [%1], 16;\n" :: "r"(dst), "l"(src));
}
#define CP_COMMIT() asm volatile("cp.async.commit_group;\n")
#define CP_WAIT1()  asm volatile("cp.async.wait_group 1;\n")

__device__ __forceinline__ void mma16(float* c,
                                      uint32_t a0, uint32_t a1, uint32_t a2, uint32_t a3,
                                      uint32_t b0, uint32_t b1) {
    asm volatile(
        "mma.sync.aligned.m16n8k16.row.col.f32.f16.f16.f32 "
        "{%0,%1,%2,%3}, {%4,%5,%6,%7}, {%8,%9}, {%0,%1,%2,%3};"
        : "+f"(c[0]), "+f"(c[1]), "+f"(c[2]), "+f"(c[3])
        : "r"(a0), "r"(a1), "r"(a2), "r"(a3), "r"(b0), "r"(b1));
}

// ==================== K1: fused projections (single-barrier, full-MLP) =======
// grid (N/64, 3): y=0 -> Q (scaled), y=1 -> K, y=2 -> V (transposed store)
// All 4 k-chunks loaded up-front (96 LDG.128/thread, no intervening barriers),
// ONE __syncthreads, then all 16 k-step mmas. 110.6 KB smem -> 2 blocks/SM.
#define LDA1 72
__global__ __launch_bounds__(128) void proj_kernel(
    const float* __restrict__ embC, const float* __restrict__ embE,
    const float* __restrict__ Wq, const float* __restrict__ bq,
    const float* __restrict__ Wk, const float* __restrict__ bk,
    const float* __restrict__ Wv, const float* __restrict__ bv)
{
    int which = blockIdx.y;
    const float* src = (which == 0) ? embC : embE;
    const float* W   = (which == 0) ? Wq : (which == 1) ? Wk : Wv;
    const float* b   = (which == 0) ? bq : (which == 1) ? bk : bv;
    float oscale     = (which == 0) ? SCALE : 1.0f;

    __shared__ __half sA4[4 * 64 * LDA1];     // 36.9 KB (emb chunks)
    __shared__ __half sBt4[4 * 128 * LDA1];   // 73.7 KB (W^T chunks)
    __half* sVs = sA4;                        // alias for V staging (18.4 KB)

    int tid = threadIdx.x, lane = tid & 31, wid = tid >> 5;
    int g = lane >> 2, tig = lane & 3;
    int r0 = blockIdx.x * 64;
    int wr0 = wid * 16;

    // ---- phase 1: load ALL chunks (no barriers between -> full MLP) ----
#pragma unroll
    for (int ch = 0; ch < 4; ch++) {
        int k0 = ch * 64;
        __half* sA = sA4 + ch * 64 * LDA1;
#pragma unroll
        for (int i = 0; i < 8; i++) {
            int idx = tid + i * 128;
            int row = idx >> 4, c4 = (idx & 15) << 2;
            float4 v = *(const float4*)&src[(size_t)(r0 + row) * IN_F + k0 + c4];
            __half tmp[4] = { __float2half(v.x), __float2half(v.y),
                              __float2half(v.z), __float2half(v.w) };
            *(uint2*)&sA[row * LDA1 + c4] = *(const uint2*)tmp;
        }
        __half* sBt = sBt4 + ch * 128 * LDA1;
#pragma unroll
        for (int i = 0; i < 16; i++) {
            int idx = tid + i * 128;
            int k = idx >> 5, n4 = (idx & 31) << 2;
            float4 v = *(const float4*)&W[(size_t)(k0 + k) * D + n4];
            sBt[(n4 + 0) * LDA1 + k] = __float2half(v.x);
            sBt[(n4 + 1) * LDA1 + k] = __float2half(v.y);
            sBt[(n4 + 2) * LDA1 + k] = __float2half(v.z);
            sBt[(n4 + 3) * LDA1 + k] = __float2half(v.w);
        }
    }
    __syncthreads();                          // single barrier before compute

    // ---- phase 2: all mmas ----
    float acc[16][4];
#pragma unroll
    for (int nf = 0; nf < 16; nf++)
#pragma unroll
        for (int c = 0; c < 4; c++) acc[nf][c] = 0.f;

#pragma unroll
    for (int ch = 0; ch < 4; ch++) {
        const __half* sA  = sA4 + ch * 64 * LDA1;
        const __half* sBt = sBt4 + ch * 128 * LDA1;
#pragma unroll
        for (int ks = 0; ks < 4; ks++) {
            int kb = ks * 16 + 2 * tig;
            uint32_t a0 = *(const uint32_t*)&sA[(wr0 + g) * LDA1 + kb];
            uint32_t a1 = *(const uint32_t*)&sA[(wr0 + 8 + g) * LDA1 + kb];
            uint32_t a2 = *(const uint32_t*)&sA[(wr0 + g) * LDA1 + kb + 8];
            uint32_t a3 = *(const uint32_t*)&sA[(wr0 + 8 + g) * LDA1 + kb + 8];
#pragma unroll
            for (int nf = 0; nf < 16; nf++) {
                uint32_t b0 = *(const uint32_t*)&sBt[(nf * 8 + g) * LDA1 + kb];
                uint32_t b1 = *(const uint32_t*)&sBt[(nf * 8 + g) * LDA1 + kb + 8];
                mma16(acc[nf], a0, a1, a2, a3, b0, b1);
            }
        }
    }

    if (which == 2) {
        __syncthreads();                      // sA4 reads done before sVs alias writes
#pragma unroll
        for (int nf = 0; nf < 16; nf++) {
            int col = nf * 8 + 2 * tig;
            float2 bb = *(const float2*)&b[col];
            sVs[(col + 0) * LDA1 + wr0 + g]     = __float2half(acc[nf][0] + bb.x);
            sVs[(col + 1) * LDA1 + wr0 + g]     = __float2half(acc[nf][1] + bb.y);
            sVs[(col + 0) * LDA1 + wr0 + 8 + g] = __float2half(acc[nf][2] + bb.x);
            sVs[(col + 1) * LDA1 + wr0 + 8 + g] = __float2half(acc[nf][3] + bb.y);
        }
        __syncthreads();
#pragma unroll
        for (int i = 0; i < 8; i++) {
            int idx = tid + i * 128;
            int d = idx >> 3, k8 = idx & 7;
            uint4 v = *(const uint4*)&sVs[d * LDA1 + k8 * 8];
            *(uint4*)&gVt[(size_t)d * N_E + r0 + k8 * 8] = v;
        }
    } else {
        __half* dst = (which == 0) ? gQh : gKh;
#pragma unroll
        for (int nf = 0; nf < 16; nf++) {
            int col = nf * 8 + 2 * tig;
            float2 bb = *(const float2*)&b[col];
            __half2 h0 = __floats2half2_rn((acc[nf][0] + bb.x) * oscale,
                                           (acc[nf][1] + bb.y) * oscale);
            __half2 h1 = __floats2half2_rn((acc[nf][2] + bb.x) * oscale,
                                           (acc[nf][3] + bb.y) * oscale);
            *(uint32_t*)&dst[(size_t)(r0 + wr0 + g) * D + col]     = *(uint32_t*)&h0;
            *(uint32_t*)&dst[(size_t)(r0 + wr0 + 8 + g) * D + col] = *(uint32_t*)&h1;
        }
    }
}

// ==================== K2: attention (EXACT R12: best 318.5us) ================
// 128 blocks x 64 rows, 512 threads = 16 warps as 4(m) x 4(n); warp tile 16x32.
__global__ __launch_bounds__(NTHR, 1) void attn_kernel(
    const int* __restrict__ mask, float* __restrict__ attn, float* __restrict__ out0)
{
    if (out0 == nullptr) out0 = gOscratch;

    extern __shared__ char sm[];
    uint32_t sb = smem_u32(sm);
    float* sRow = (float*)(sm + ROWOFF);
    float* sInv = (float*)(sm + INVOFF);

    int tid  = threadIdx.x;
    int lane = tid & 31, wid = tid >> 5;
    int g = lane >> 2, tig = lane & 3;
    int wm = wid >> 2, wn = wid & 3;       // 4 m-groups x 4 n-groups
    int i0 = blockIdx.x * BM;

    if (tid < 64) sRow[tid] = 0.f;

    int mrow = wm * 16 + g;                // local row (partner row adds 8)
    int ncol0 = wn * 32;                   // S-phase col base / PV-phase d base

    // ---- Q tile (64 x 128 halves) ----
#pragma unroll
    for (int k = 0; k < 2; k++) {
        int t = tid + k * NTHR;
        int r = t >> 4, cc = t & 15;
        uint4 v = *(const uint4*)&gQh[(size_t)(i0 + r) * D + cc * 8];
        *(uint4*)(sm + QOFF + r * LDB + cc * 16) = v;
    }

    const uint32_t kbuf[2] = { sb + KOFF0, sb + KOFF1 };
    const uint32_t vbuf[2] = { sb + VOFF0, sb + VOFF1 };
#pragma unroll
    for (int k = 0; k < 4; k++) {
        int c = tid + k * NTHR;
        int row = c >> 4, cc = c & 15;
        cpa16(kbuf[0] + row * LDB + cc * 16, &gKh[(size_t)row * D + cc * 8]);
        cpa16(vbuf[0] + row * LDB + cc * 16, &gVt[(size_t)row * N_E + cc * 8]);
    }
    CP_COMMIT();
#pragma unroll
    for (int k = 0; k < 4; k++) {
        int c = tid + k * NTHR;
        int row = c >> 4, cc = c & 15;
        cpa16(kbuf[1] + row * LDB + cc * 16, &gKh[(size_t)(BN + row) * D + cc * 8]);
        cpa16(vbuf[1] + row * LDB + cc * 16, &gVt[(size_t)row * N_E + BN + cc * 8]);
    }
    CP_COMMIT();

    float oAcc[4][4];                      // 16 rows x 32 d
#pragma unroll
    for (int ni = 0; ni < 4; ni++)
#pragma unroll
        for (int c = 0; c < 4; c++) oAcc[ni][c] = 0.f;
    float rs0 = 0.f, rs1 = 0.f;

    for (int jt = 0; jt < NT; jt++) {
        int j0 = jt * BN;
        uint32_t sK = kbuf[jt & 1], sV = vbuf[jt & 1];

        CP_WAIT1();
        __syncthreads();                   // tile jt resident

        // ---- mask prefetch (hidden under S mma) ----
        int2 mreg[4][2];
#pragma unroll
        for (int ni = 0; ni < 4; ni++) {
            size_t gr0 = (size_t)(i0 + mrow) * N_E + j0 + ncol0 + ni * 8 + 2 * tig;
            mreg[ni][0] = *(const int2*)&mask[gr0];
            mreg[ni][1] = *(const int2*)&mask[gr0 + 8 * N_E];
        }

        // ---- S = Q @ K^T  (k = 128) ----
        float sAcc[4][4];
#pragma unroll
        for (int ni = 0; ni < 4; ni++)
#pragma unroll
            for (int c = 0; c < 4; c++) sAcc[ni][c] = 0.f;

#pragma unroll
        for (int ks = 0; ks < 8; ks++) {
            int kb = (ks * 16 + 2 * tig) * 2;
            uint32_t ro = (uint32_t)mrow * LDB;
            uint32_t a0 = *(const uint32_t*)(sm + QOFF + ro + kb);
            uint32_t a1 = *(const uint32_t*)(sm + QOFF + ro + 8 * LDB + kb);
            uint32_t a2 = *(const uint32_t*)(sm + QOFF + ro + kb + 16);
            uint32_t a3 = *(const uint32_t*)(sm + QOFF + ro + 8 * LDB + kb + 16);
#pragma unroll
            for (int ni = 0; ni < 4; ni++) {
                uint32_t rb = (uint32_t)(ncol0 + ni * 8 + g) * LDB;
                uint32_t b0 = *(const uint32_t*)((char*)sm + (sK - sb) + rb + kb);
                uint32_t b1 = *(const uint32_t*)((char*)sm + (sK - sb) + rb + kb + 16);
                mma16(sAcc[ni], a0, a1, a2, a3, b0, b1);
            }
        }

        // ---- epilogue: mask + exp, fill sP, rowsum ----
#pragma unroll
        for (int ni = 0; ni < 4; ni++) {
            int lc = ncol0 + ni * 8 + 2 * tig;
            float p0 = mreg[ni][0].x ? __expf(sAcc[ni][0]) : 0.f;
            float p1 = mreg[ni][0].y ? __expf(sAcc[ni][1]) : 0.f;
            float p2 = mreg[ni][1].x ? __expf(sAcc[ni][2]) : 0.f;
            float p3 = mreg[ni][1].y ? __expf(sAcc[ni][3]) : 0.f;
            rs0 += p0 + p1;
            rs1 += p2 + p3;
            __half2 h0 = __floats2half2_rn(p0, p1);
            __half2 h1 = __floats2half2_rn(p2, p3);
            *(uint32_t*)(sm + POFF + mrow * LDB + lc * 2)       = *(uint32_t*)&h0;
            *(uint32_t*)(sm + POFF + (mrow + 8) * LDB + lc * 2) = *(uint32_t*)&h1;
        }
        __syncthreads();                   // sP complete; K reads all done

        // ---- K prefetch for jt+2 (K buffer jt&1 is free now) ----
        if (jt + 2 < NT) {
            int jn = (jt + 2) * BN;
            uint32_t kb2 = kbuf[jt & 1];
#pragma unroll
            for (int k = 0; k < 4; k++) {
                int c = tid + k * NTHR;
                int row = c >> 4, cc = c & 15;
                cpa16(kb2 + row * LDB + cc * 16, &gKh[(size_t)(jn + row) * D + cc * 8]);
            }
        }

        // ---- coalesced sP -> gPstage copy (full 32B sectors) ----
#pragma unroll
        for (int k = 0; k < 2; k++) {
            int t = tid + k * NTHR;
            int r = t >> 4, cc = t & 15;
            uint4 v = *(const uint4*)(sm + POFF + r * LDB + cc * 16);
            *(uint4*)&gPstage[(size_t)(i0 + r) * N_E + j0 + cc * 8] = v;
        }

        // ---- O += P @ V  (k = 128 keys, warp covers 32 d) ----
#pragma unroll
        for (int ks = 0; ks < 8; ks++) {
            int kb = (ks * 16 + 2 * tig) * 2;
            uint32_t ro = (uint32_t)mrow * LDB;
            uint32_t a0 = *(const uint32_t*)(sm + POFF + ro + kb);
            uint32_t a1 = *(const uint32_t*)(sm + POFF + ro + 8 * LDB + kb);
            uint32_t a2 = *(const uint32_t*)(sm + POFF + ro + kb + 16);
            uint32_t a3 = *(const uint32_t*)(sm + POFF + ro + 8 * LDB + kb + 16);
#pragma unroll
            for (int ni = 0; ni < 4; ni++) {
                uint32_t rb = (uint32_t)(ncol0 + ni * 8 + g) * LDB;  // d row
                uint32_t b0 = *(const uint32_t*)((char*)sm + (sV - sb) + rb + kb);
                uint32_t b1 = *(const uint32_t*)((char*)sm + (sV - sb) + rb + kb + 16);
                mma16(oAcc[ni], a0, a1, a2, a3, b0, b1);
            }
        }
        __syncthreads();                   // V reads done

        // ---- V prefetch for jt+2 ----
        if (jt + 2 < NT) {
            int jn = (jt + 2) * BN;
            uint32_t vb2 = vbuf[jt & 1];
#pragma unroll
            for (int k = 0; k < 4; k++) {
                int c = tid + k * NTHR;
                int row = c >> 4, cc = c & 15;
                cpa16(vb2 + row * LDB + cc * 16, &gVt[(size_t)row * N_E + jn + cc * 8]);
            }
        }
        CP_COMMIT();                       // one group per iteration (K+V)
    }

    // ---- rowsum reduce -> inv (4 n-warps contribute per row) ----
    {
        float v0 = rs0, v1 = rs1;
        v0 += __shfl_xor_sync(0xffffffffu, v0, 1);
        v0 += __shfl_xor_sync(0xffffffffu, v0, 2);
        v1 += __shfl_xor_sync(0xffffffffu, v1, 1);
        v1 += __shfl_xor_sync(0xffffffffu, v1, 2);
        if (tig == 0) {
            atomicAdd(&sRow[wm * 16 + g], v0);
            atomicAdd(&sRow[wm * 16 + 8 + g], v1);
        }
    }
    __syncthreads();
    if (tid < 64) sInv[tid] = 1.0f / sRow[tid];
    __syncthreads();

    // ---- write normalized O (warp owns rows wm*16.., d cols wn*32..) ----
    {
        float iv0 = sInv[mrow], iv1 = sInv[mrow + 8];
#pragma unroll
        for (int ni = 0; ni < 4; ni++) {
            int c = ncol0 + ni * 8 + 2 * tig;
            *(float2*)&out0[(size_t)(i0 + mrow) * D + c] =
                make_float2(oAcc[ni][0] * iv0, oAcc[ni][1] * iv0);
            *(float2*)&out0[(size_t)(i0 + mrow + 8) * D + c] =
                make_float2(oAcc[ni][2] * iv1, oAcc[ni][3] * iv1);
        }
    }

    // ---- fused normalization: fp16 stage -> fp32 attn, fully coalesced ----
    const __half* pst = gPstage + (size_t)i0 * N_E;
    float4* a4 = (float4*)(attn + (size_t)i0 * N_E);
    const int totalc = 64 * (N_E / 4);     // 131072 uint2 chunks = 512*8*32
    for (int base = 0; base < totalc; base += NTHR * 8) {
        uint2 v[8];
        int idx[8];
#pragma unroll
        for (int u = 0; u < 8; u++) {
            idx[u] = base + u * NTHR + tid;
            v[u] = *(const uint2*)&pst[(size_t)idx[u] * 4];
        }
#pragma unroll
        for (int u = 0; u < 8; u++) {
            float inv = sInv[idx[u] >> 11];    // 2048 uint2 per row
            const __half2* h2 = (const __half2*)&v[u];
            float2 f0 = __half22float2(h2[0]);
            float2 f1 = __half22float2(h2[1]);
            a4[idx[u]] = make_float4(f0.x * inv, f0.y * inv, f1.x * inv, f1.y * inv);
        }
    }
}

// ==================== host ====================
extern "C" void kernel_launch(void* const* d_in, const int* in_sizes, int n_in,
                              void* d_out, int out_size)
{
    const float* embC = (const float*)d_in[0];
    const float* embE = (const float*)d_in[1];
    const int*   mask = (const int*)d_in[2];
    const float* Wq = (const float*)d_in[3];
    const float* bq = (const float*)d_in[4];
    const float* Wk = (const float*)d_in[5];
    const float* bk = (const float*)d_in[6];
    const float* Wv = (const float*)d_in[7];
    const float* bv = (const float*)d_in[8];

    float* base = (float*)d_out;
    long long t2 = (long long)N_C * N_E;

    float* out0;
    float* attn;
    if ((long long)out_size == t2) {
        out0 = nullptr;
        attn = base;
    } else {
        out0 = base;
        attn = base + (long long)N_C * D;
    }

    dim3 pgrid(N_C / 64, 3);
    proj_kernel<<<pgrid, 128>>>(embC, embE, Wq, bq, Wk, bk, Wv, bv);

    static int configured = 0;
    if (!configured) {
        cudaFuncSetAttribute(attn_kernel, cudaFuncAttributeMaxDynamicSharedMemorySize, SMEM_TOTAL);
        configured = 1;
    }
    attn_kernel<<<N_C / BM, NTHR, SMEM_TOTAL>>>(mask, attn, out0);
}

// round 15
// speedup vs baseline: 1.0747x; 1.0746x over previous
#include <cuda_runtime.h>
#include <cuda_fp16.h>
#include <cstdint>

#define N_C 8192
#define N_E 8192
#define IN_F 256
#define D 128
#define SCALE 0.08838834764831845f  /* 1/sqrt(128) */

#define BM 64            /* rows per block (attn) */
#define BN 128           /* cols per tile (attn) */
#define NT (N_E / BN)    /* 64 tiles */
#define LDH 136          /* attn smem leading dim in halves */
#define LDB (LDH * 2)    /* bytes: 272 */
#define NTHR 512         /* 16 warps */

// -------- device scratch (static: no allocation allowed) --------
__device__ __half gQh[N_C * D];              // pre-scaled
__device__ __half gKh[N_E * D];              // row-major [key][d]
__device__ __half gVt[D * N_E];              // TRANSPOSED [d][key]
__device__ __half gPstage[(size_t)N_C * N_E]; // fp16 unnormalized attn staging
__device__ float  gOscratch[N_C * D];

// smem byte offsets for attn kernel (174.6 KB -> ~53 KB L1D left)
#define QOFF   0
#define KOFF0  17408
#define KOFF1  (17408 + 34816)
#define VOFF0  (17408 + 69632)
#define VOFF1  (17408 + 69632 + 34816)
#define POFF   (17408 + 139264)
#define ROWOFF (POFF + 17408)
#define INVOFF (ROWOFF + 256)
#define SMEM_TOTAL (INVOFF + 256)

// -------- helpers --------
__device__ __forceinline__ uint32_t smem_u32(const void* p) {
    uint32_t a;
    asm("{ .reg .u64 t; cvta.to.shared.u64 t, %1; cvt.u32.u64 %0, t; }" : "=r"(a) : "l"(p));
    return a;
}
__device__ __forceinline__ void cpa16(uint32_t dst, const void* src) {
    asm volatile("cp.async.cg.shared.global [%0], [%1], 16;\n" :: "r"(dst), "l"(src));
}
#define CP_COMMIT() asm volatile("cp.async.commit_group;\n")
#define CP_WAIT1()  asm volatile("cp.async.wait_group 1;\n")

__device__ __forceinline__ void mma16(float* c,
                                      uint32_t a0, uint32_t a1, uint32_t a2, uint32_t a3,
                                      uint32_t b0, uint32_t b1) {
    asm volatile(
        "mma.sync.aligned.m16n8k16.row.col.f32.f16.f16.f32 "
        "{%0,%1,%2,%3}, {%4,%5,%6,%7}, {%8,%9}, {%0,%1,%2,%3};"
        : "+f"(c[0]), "+f"(c[1]), "+f"(c[2]), "+f"(c[3])
        : "r"(a0), "r"(a1), "r"(a2), "r"(a3), "r"(b0), "r"(b1));
}

// ==================== K1: fused projections via fp16 mma (R12 proven) ========
#define LDA1 72
__global__ __launch_bounds__(128) void proj_kernel(
    const float* __restrict__ embC, const float* __restrict__ embE,
    const float* __restrict__ Wq, const float* __restrict__ bq,
    const float* __restrict__ Wk, const float* __restrict__ bk,
    const float* __restrict__ Wv, const float* __restrict__ bv)
{
    int which = blockIdx.y;
    const float* src = (which == 0) ? embC : embE;
    const float* W   = (which == 0) ? Wq : (which == 1) ? Wk : Wv;
    const float* b   = (which == 0) ? bq : (which == 1) ? bk : bv;
    float oscale     = (which == 0) ? SCALE : 1.0f;

    __shared__ __half sA[64 * LDA1];
    __shared__ __half sBt[128 * LDA1];
    __shared__ __half sVs[128 * LDA1];

    int tid = threadIdx.x, lane = tid & 31, wid = tid >> 5;
    int g = lane >> 2, tig = lane & 3;
    int r0 = blockIdx.x * 64;
    int wr0 = wid * 16;

    float acc[16][4];
#pragma unroll
    for (int nf = 0; nf < 16; nf++)
#pragma unroll
        for (int c = 0; c < 4; c++) acc[nf][c] = 0.f;

    for (int ch = 0; ch < 4; ch++) {
        int k0 = ch * 64;
        __syncthreads();
#pragma unroll
        for (int i = 0; i < 8; i++) {
            int idx = tid + i * 128;
            int row = idx >> 4, c4 = (idx & 15) << 2;
            float4 v = *(const float4*)&src[(size_t)(r0 + row) * IN_F + k0 + c4];
            __half tmp[4] = { __float2half(v.x), __float2half(v.y),
                              __float2half(v.z), __float2half(v.w) };
            *(uint2*)&sA[row * LDA1 + c4] = *(const uint2*)tmp;
        }
#pragma unroll
        for (int i = 0; i < 16; i++) {
            int idx = tid + i * 128;
            int k = idx >> 5, n4 = (idx & 31) << 2;
            float4 v = *(const float4*)&W[(size_t)(k0 + k) * D + n4];
            sBt[(n4 + 0) * LDA1 + k] = __float2half(v.x);
            sBt[(n4 + 1) * LDA1 + k] = __float2half(v.y);
            sBt[(n4 + 2) * LDA1 + k] = __float2half(v.z);
            sBt[(n4 + 3) * LDA1 + k] = __float2half(v.w);
        }
        __syncthreads();
#pragma unroll
        for (int ks = 0; ks < 4; ks++) {
            int kb = ks * 16 + 2 * tig;
            uint32_t a0 = *(const uint32_t*)&sA[(wr0 + g) * LDA1 + kb];
            uint32_t a1 = *(const uint32_t*)&sA[(wr0 + 8 + g) * LDA1 + kb];
            uint32_t a2 = *(const uint32_t*)&sA[(wr0 + g) * LDA1 + kb + 8];
            uint32_t a3 = *(const uint32_t*)&sA[(wr0 + 8 + g) * LDA1 + kb + 8];
#pragma unroll
            for (int nf = 0; nf < 16; nf++) {
                uint32_t b0 = *(const uint32_t*)&sBt[(nf * 8 + g) * LDA1 + kb];
                uint32_t b1 = *(const uint32_t*)&sBt[(nf * 8 + g) * LDA1 + kb + 8];
                mma16(acc[nf], a0, a1, a2, a3, b0, b1);
            }
        }
    }

    if (which == 2) {
#pragma unroll
        for (int nf = 0; nf < 16; nf++) {
            int col = nf * 8 + 2 * tig;
            float2 bb = *(const float2*)&b[col];
            sVs[(col + 0) * LDA1 + wr0 + g]     = __float2half(acc[nf][0] + bb.x);
            sVs[(col + 1) * LDA1 + wr0 + g]     = __float2half(acc[nf][1] + bb.y);
            sVs[(col + 0) * LDA1 + wr0 + 8 + g] = __float2half(acc[nf][2] + bb.x);
            sVs[(col + 1) * LDA1 + wr0 + 8 + g] = __float2half(acc[nf][3] + bb.y);
        }
        __syncthreads();
#pragma unroll
        for (int i = 0; i < 8; i++) {
            int idx = tid + i * 128;
            int d = idx >> 3, k8 = idx & 7;
            uint4 v = *(const uint4*)&sVs[d * LDA1 + k8 * 8];
            *(uint4*)&gVt[(size_t)d * N_E + r0 + k8 * 8] = v;
        }
    } else {
        __half* dst = (which == 0) ? gQh : gKh;
#pragma unroll
        for (int nf = 0; nf < 16; nf++) {
            int col = nf * 8 + 2 * tig;
            float2 bb = *(const float2*)&b[col];
            __half2 h0 = __floats2half2_rn((acc[nf][0] + bb.x) * oscale,
                                           (acc[nf][1] + bb.y) * oscale);
            __half2 h1 = __floats2half2_rn((acc[nf][2] + bb.x) * oscale,
                                           (acc[nf][3] + bb.y) * oscale);
            *(uint32_t*)&dst[(size_t)(r0 + wr0 + g) * D + col]     = *(uint32_t*)&h0;
            *(uint32_t*)&dst[(size_t)(r0 + wr0 + 8 + g) * D + col] = *(uint32_t*)&h1;
        }
    }
}

// ==================== K2: attention (R12 + copy-after-PV reorder) ============
// 128 blocks x 64 rows, 512 threads = 16 warps as 4(m) x 4(n); warp tile 16x32.
__global__ __launch_bounds__(NTHR, 1) void attn_kernel(
    const int* __restrict__ mask, float* __restrict__ attn, float* __restrict__ out0)
{
    if (out0 == nullptr) out0 = gOscratch;

    extern __shared__ char sm[];
    uint32_t sb = smem_u32(sm);
    float* sRow = (float*)(sm + ROWOFF);
    float* sInv = (float*)(sm + INVOFF);

    int tid  = threadIdx.x;
    int lane = tid & 31, wid = tid >> 5;
    int g = lane >> 2, tig = lane & 3;
    int wm = wid >> 2, wn = wid & 3;       // 4 m-groups x 4 n-groups
    int i0 = blockIdx.x * BM;

    if (tid < 64) sRow[tid] = 0.f;

    int mrow = wm * 16 + g;                // local row (partner row adds 8)
    int ncol0 = wn * 32;                   // S-phase col base / PV-phase d base

    // ---- Q tile (64 x 128 halves) ----
#pragma unroll
    for (int k = 0; k < 2; k++) {
        int t = tid + k * NTHR;
        int r = t >> 4, cc = t & 15;
        uint4 v = *(const uint4*)&gQh[(size_t)(i0 + r) * D + cc * 8];
        *(uint4*)(sm + QOFF + r * LDB + cc * 16) = v;
    }

    const uint32_t kbuf[2] = { sb + KOFF0, sb + KOFF1 };
    const uint32_t vbuf[2] = { sb + VOFF0, sb + VOFF1 };
#pragma unroll
    for (int k = 0; k < 4; k++) {
        int c = tid + k * NTHR;
        int row = c >> 4, cc = c & 15;
        cpa16(kbuf[0] + row * LDB + cc * 16, &gKh[(size_t)row * D + cc * 8]);
        cpa16(vbuf[0] + row * LDB + cc * 16, &gVt[(size_t)row * N_E + cc * 8]);
    }
    CP_COMMIT();
#pragma unroll
    for (int k = 0; k < 4; k++) {
        int c = tid + k * NTHR;
        int row = c >> 4, cc = c & 15;
        cpa16(kbuf[1] + row * LDB + cc * 16, &gKh[(size_t)(BN + row) * D + cc * 8]);
        cpa16(vbuf[1] + row * LDB + cc * 16, &gVt[(size_t)row * N_E + BN + cc * 8]);
    }
    CP_COMMIT();

    float oAcc[4][4];                      // 16 rows x 32 d
#pragma unroll
    for (int ni = 0; ni < 4; ni++)
#pragma unroll
        for (int c = 0; c < 4; c++) oAcc[ni][c] = 0.f;
    float rs0 = 0.f, rs1 = 0.f;

    for (int jt = 0; jt < NT; jt++) {
        int j0 = jt * BN;
        uint32_t sK = kbuf[jt & 1], sV = vbuf[jt & 1];

        CP_WAIT1();
        __syncthreads();                   // tile jt resident

        // ---- mask prefetch (hidden under S mma) ----
        int2 mreg[4][2];
#pragma unroll
        for (int ni = 0; ni < 4; ni++) {
            size_t gr0 = (size_t)(i0 + mrow) * N_E + j0 + ncol0 + ni * 8 + 2 * tig;
            mreg[ni][0] = *(const int2*)&mask[gr0];
            mreg[ni][1] = *(const int2*)&mask[gr0 + 8 * N_E];
        }

        // ---- S = Q @ K^T  (k = 128) ----
        float sAcc[4][4];
#pragma unroll
        for (int ni = 0; ni < 4; ni++)
#pragma unroll
            for (int c = 0; c < 4; c++) sAcc[ni][c] = 0.f;

#pragma unroll
        for (int ks = 0; ks < 8; ks++) {
            int kb = (ks * 16 + 2 * tig) * 2;
            uint32_t ro = (uint32_t)mrow * LDB;
            uint32_t a0 = *(const uint32_t*)(sm + QOFF + ro + kb);
            uint32_t a1 = *(const uint32_t*)(sm + QOFF + ro + 8 * LDB + kb);
            uint32_t a2 = *(const uint32_t*)(sm + QOFF + ro + kb + 16);
            uint32_t a3 = *(const uint32_t*)(sm + QOFF + ro + 8 * LDB + kb + 16);
#pragma unroll
            for (int ni = 0; ni < 4; ni++) {
                uint32_t rb = (uint32_t)(ncol0 + ni * 8 + g) * LDB;
                uint32_t b0 = *(const uint32_t*)((char*)sm + (sK - sb) + rb + kb);
                uint32_t b1 = *(const uint32_t*)((char*)sm + (sK - sb) + rb + kb + 16);
                mma16(sAcc[ni], a0, a1, a2, a3, b0, b1);
            }
        }

        // ---- epilogue: mask + exp, fill sP, rowsum ----
#pragma unroll
        for (int ni = 0; ni < 4; ni++) {
            int lc = ncol0 + ni * 8 + 2 * tig;
            float p0 = mreg[ni][0].x ? __expf(sAcc[ni][0]) : 0.f;
            float p1 = mreg[ni][0].y ? __expf(sAcc[ni][1]) : 0.f;
            float p2 = mreg[ni][1].x ? __expf(sAcc[ni][2]) : 0.f;
            float p3 = mreg[ni][1].y ? __expf(sAcc[ni][3]) : 0.f;
            rs0 += p0 + p1;
            rs1 += p2 + p3;
            __half2 h0 = __floats2half2_rn(p0, p1);
            __half2 h1 = __floats2half2_rn(p2, p3);
            *(uint32_t*)(sm + POFF + mrow * LDB + lc * 2)       = *(uint32_t*)&h0;
            *(uint32_t*)(sm + POFF + (mrow + 8) * LDB + lc * 2) = *(uint32_t*)&h1;
        }
        __syncthreads();                   // sP complete; K reads all done

        // ---- K prefetch for jt+2 (K buffer jt&1 is free now) ----
        if (jt + 2 < NT) {
            int jn = (jt + 2) * BN;
            uint32_t kb2 = kbuf[jt & 1];
#pragma unroll
            for (int k = 0; k < 4; k++) {
                int c = tid + k * NTHR;
                int row = c >> 4, cc = c & 15;
                cpa16(kb2 + row * LDB + cc * 16, &gKh[(size_t)(jn + row) * D + cc * 8]);
            }
        }

        // ---- O += P @ V  (k = 128 keys, warp covers 32 d) ----
#pragma unroll
        for (int ks = 0; ks < 8; ks++) {
            int kb = (ks * 16 + 2 * tig) * 2;
            uint32_t ro = (uint32_t)mrow * LDB;
            uint32_t a0 = *(const uint32_t*)(sm + POFF + ro + kb);
            uint32_t a1 = *(const uint32_t*)(sm + POFF + ro + 8 * LDB + kb);
            uint32_t a2 = *(const uint32_t*)(sm + POFF + ro + kb + 16);
            uint32_t a3 = *(const uint32_t*)(sm + POFF + ro + 8 * LDB + kb + 16);
#pragma unroll
            for (int ni = 0; ni < 4; ni++) {
                uint32_t rb = (uint32_t)(ncol0 + ni * 8 + g) * LDB;  // d row
                uint32_t b0 = *(const uint32_t*)((char*)sm + (sV - sb) + rb + kb);
                uint32_t b1 = *(const uint32_t*)((char*)sm + (sV - sb) + rb + kb + 16);
                mma16(oAcc[ni], a0, a1, a2, a3, b0, b1);
            }
        }

        // ---- coalesced sP -> gPstage copy (after PV: off the critical path) ----
#pragma unroll
        for (int k = 0; k < 2; k++) {
            int t = tid + k * NTHR;
            int r = t >> 4, cc = t & 15;
            uint4 v = *(const uint4*)(sm + POFF + r * LDB + cc * 16);
            *(uint4*)&gPstage[(size_t)(i0 + r) * N_E + j0 + cc * 8] = v;
        }
        __syncthreads();                   // V reads done

        // ---- V prefetch for jt+2 ----
        if (jt + 2 < NT) {
            int jn = (jt + 2) * BN;
            uint32_t vb2 = vbuf[jt & 1];
#pragma unroll
            for (int k = 0; k < 4; k++) {
                int c = tid + k * NTHR;
                int row = c >> 4, cc = c & 15;
                cpa16(vb2 + row * LDB + cc * 16, &gVt[(size_t)row * N_E + jn + cc * 8]);
            }
        }
        CP_COMMIT();                       // one group per iteration (K+V)
    }

    // ---- rowsum reduce -> inv (4 n-warps contribute per row) ----
    {
        float v0 = rs0, v1 = rs1;
        v0 += __shfl_xor_sync(0xffffffffu, v0, 1);
        v0 += __shfl_xor_sync(0xffffffffu, v0, 2);
        v1 += __shfl_xor_sync(0xffffffffu, v1, 1);
        v1 += __shfl_xor_sync(0xffffffffu, v1, 2);
        if (tig == 0) {
            atomicAdd(&sRow[wm * 16 + g], v0);
            atomicAdd(&sRow[wm * 16 + 8 + g], v1);
        }
    }
    __syncthreads();
    if (tid < 64) sInv[tid] = 1.0f / sRow[tid];
    __syncthreads();

    // ---- write normalized O (warp owns rows wm*16.., d cols wn*32..) ----
    {
        float iv0 = sInv[mrow], iv1 = sInv[mrow + 8];
#pragma unroll
        for (int ni = 0; ni < 4; ni++) {
            int c = ncol0 + ni * 8 + 2 * tig;
            *(float2*)&out0[(size_t)(i0 + mrow) * D + c] =
                make_float2(oAcc[ni][0] * iv0, oAcc[ni][1] * iv0);
            *(float2*)&out0[(size_t)(i0 + mrow + 8) * D + c] =
                make_float2(oAcc[ni][2] * iv1, oAcc[ni][3] * iv1);
        }
    }

    // ---- fused normalization: fp16 stage -> fp32 attn, fully coalesced ----
    const __half* pst = gPstage + (size_t)i0 * N_E;
    float4* a4 = (float4*)(attn + (size_t)i0 * N_E);
    const int totalc = 64 * (N_E / 4);     // 131072 uint2 chunks = 512*8*32
    for (int base = 0; base < totalc; base += NTHR * 8) {
        uint2 v[8];
        int idx[8];
#pragma unroll
        for (int u = 0; u < 8; u++) {
            idx[u] = base + u * NTHR + tid;
            v[u] = *(const uint2*)&pst[(size_t)idx[u] * 4];
        }
#pragma unroll
        for (int u = 0; u < 8; u++) {
            float inv = sInv[idx[u] >> 11];    // 2048 uint2 per row
            const __half2* h2 = (const __half2*)&v[u];
            float2 f0 = __half22float2(h2[0]);
            float2 f1 = __half22float2(h2[1]);
            a4[idx[u]] = make_float4(f0.x * inv, f0.y * inv, f1.x * inv, f1.y * inv);
        }
    }
}

// ==================== host ====================
extern "C" void kernel_launch(void* const* d_in, const int* in_sizes, int n_in,
                              void* d_out, int out_size)
{
    const float* embC = (const float*)d_in[0];
    const float* embE = (const float*)d_in[1];
    const int*   mask = (const int*)d_in[2];
    const float* Wq = (const float*)d_in[3];
    const float* bq = (const float*)d_in[4];
    const float* Wk = (const float*)d_in[5];
    const float* bk = (const float*)d_in[6];
    const float* Wv = (const float*)d_in[7];
    const float* bv = (const float*)d_in[8];

    float* base = (float*)d_out;
    long long t2 = (long long)N_C * N_E;

    float* out0;
    float* attn;
    if ((long long)out_size == t2) {
        out0 = nullptr;
        attn = base;
    } else {
        out0 = base;
        attn = base + (long long)N_C * D;
    }

    dim3 pgrid(N_C / 64, 3);
    proj_kernel<<<pgrid, 128>>>(embC, embE, Wq, bq, Wk, bk, Wv, bv);

    static int configured = 0;
    if (!configured) {
        cudaFuncSetAttribute(attn_kernel, cudaFuncAttributeMaxDynamicSharedMemorySize, SMEM_TOTAL);
        configured = 1;
    }
    attn_kernel<<<N_C / BM, NTHR, SMEM_TOTAL>>>(mask, attn, out0);
}

// round 16
// speedup vs baseline: 1.1202x; 1.0424x over previous
#include <cuda_runtime.h>
#include <cuda_fp16.h>
#include <cstdint>

#define N_C 8192
#define N_E 8192
#define IN_F 256
#define D 128
#define SCALE 0.08838834764831845f  /* 1/sqrt(128) */

#define BM 64            /* rows per block (attn) */
#define BN 128           /* cols per tile (attn) */
#define NT (N_E / BN)    /* 64 tiles */
#define LDH 136          /* attn smem leading dim in halves */
#define LDB (LDH * 2)    /* bytes: 272 */
#define NTHR 512         /* 16 warps */

// -------- device scratch (static: no allocation allowed) --------
__device__ __half gQh[N_C * D];              // pre-scaled
__device__ __half gKh[N_E * D];              // row-major [key][d]
__device__ __half gVt[D * N_E];              // TRANSPOSED [d][key]
__device__ __half gPstage[(size_t)N_C * N_E]; // fp16 unnormalized attn staging
__device__ float  gOscratch[N_C * D];

// smem byte offsets for attn kernel (174.6 KB -> ~53 KB L1D left)
#define QOFF   0
#define KOFF0  17408
#define KOFF1  (17408 + 34816)
#define VOFF0  (17408 + 69632)
#define VOFF1  (17408 + 69632 + 34816)
#define POFF   (17408 + 139264)
#define ROWOFF (POFF + 17408)
#define INVOFF (ROWOFF + 256)
#define SMEM_TOTAL (INVOFF + 256)

// -------- helpers --------
__device__ __forceinline__ uint32_t smem_u32(const void* p) {
    uint32_t a;
    asm("{ .reg .u64 t; cvta.to.shared.u64 t, %1; cvt.u32.u64 %0, t; }" : "=r"(a) : "l"(p));
    return a;
}
__device__ __forceinline__ void cpa16(uint32_t dst, const void* src) {
    asm volatile("cp.async.cg.shared.global [%0], [%1], 16;\n" :: "r"(dst), "l"(src));
}
#define CP_COMMIT() asm volatile("cp.async.commit_group;\n")
#define CP_WAIT0()  asm volatile("cp.async.wait_group 0;\n")

__device__ __forceinline__ void mma16(float* c,
                                      uint32_t a0, uint32_t a1, uint32_t a2, uint32_t a3,
                                      uint32_t b0, uint32_t b1) {
    asm volatile(
        "mma.sync.aligned.m16n8k16.row.col.f32.f16.f16.f32 "
        "{%0,%1,%2,%3}, {%4,%5,%6,%7}, {%8,%9}, {%0,%1,%2,%3};"
        : "+f"(c[0]), "+f"(c[1]), "+f"(c[2]), "+f"(c[3])
        : "r"(a0), "r"(a1), "r"(a2), "r"(a3), "r"(b0), "r"(b1));
}

// ==================== K1: fused projections via fp16 mma (R12 proven) ========
#define LDA1 72
__global__ __launch_bounds__(128) void proj_kernel(
    const float* __restrict__ embC, const float* __restrict__ embE,
    const float* __restrict__ Wq, const float* __restrict__ bq,
    const float* __restrict__ Wk, const float* __restrict__ bk,
    const float* __restrict__ Wv, const float* __restrict__ bv)
{
    int which = blockIdx.y;
    const float* src = (which == 0) ? embC : embE;
    const float* W   = (which == 0) ? Wq : (which == 1) ? Wk : Wv;
    const float* b   = (which == 0) ? bq : (which == 1) ? bk : bv;
    float oscale     = (which == 0) ? SCALE : 1.0f;

    __shared__ __half sA[64 * LDA1];
    __shared__ __half sBt[128 * LDA1];
    __shared__ __half sVs[128 * LDA1];

    int tid = threadIdx.x, lane = tid & 31, wid = tid >> 5;
    int g = lane >> 2, tig = lane & 3;
    int r0 = blockIdx.x * 64;
    int wr0 = wid * 16;

    float acc[16][4];
#pragma unroll
    for (int nf = 0; nf < 16; nf++)
#pragma unroll
        for (int c = 0; c < 4; c++) acc[nf][c] = 0.f;

    for (int ch = 0; ch < 4; ch++) {
        int k0 = ch * 64;
        __syncthreads();
#pragma unroll
        for (int i = 0; i < 8; i++) {
            int idx = tid + i * 128;
            int row = idx >> 4, c4 = (idx & 15) << 2;
            float4 v = *(const float4*)&src[(size_t)(r0 + row) * IN_F + k0 + c4];
            __half tmp[4] = { __float2half(v.x), __float2half(v.y),
                              __float2half(v.z), __float2half(v.w) };
            *(uint2*)&sA[row * LDA1 + c4] = *(const uint2*)tmp;
        }
#pragma unroll
        for (int i = 0; i < 16; i++) {
            int idx = tid + i * 128;
            int k = idx >> 5, n4 = (idx & 31) << 2;
            float4 v = *(const float4*)&W[(size_t)(k0 + k) * D + n4];
            sBt[(n4 + 0) * LDA1 + k] = __float2half(v.x);
            sBt[(n4 + 1) * LDA1 + k] = __float2half(v.y);
            sBt[(n4 + 2) * LDA1 + k] = __float2half(v.z);
            sBt[(n4 + 3) * LDA1 + k] = __float2half(v.w);
        }
        __syncthreads();
#pragma unroll
        for (int ks = 0; ks < 4; ks++) {
            int kb = ks * 16 + 2 * tig;
            uint32_t a0 = *(const uint32_t*)&sA[(wr0 + g) * LDA1 + kb];
            uint32_t a1 = *(const uint32_t*)&sA[(wr0 + 8 + g) * LDA1 + kb];
            uint32_t a2 = *(const uint32_t*)&sA[(wr0 + g) * LDA1 + kb + 8];
            uint32_t a3 = *(const uint32_t*)&sA[(wr0 + 8 + g) * LDA1 + kb + 8];
#pragma unroll
            for (int nf = 0; nf < 16; nf++) {
                uint32_t b0 = *(const uint32_t*)&sBt[(nf * 8 + g) * LDA1 + kb];
                uint32_t b1 = *(const uint32_t*)&sBt[(nf * 8 + g) * LDA1 + kb + 8];
                mma16(acc[nf], a0, a1, a2, a3, b0, b1);
            }
        }
    }

    if (which == 2) {
#pragma unroll
        for (int nf = 0; nf < 16; nf++) {
            int col = nf * 8 + 2 * tig;
            float2 bb = *(const float2*)&b[col];
            sVs[(col + 0) * LDA1 + wr0 + g]     = __float2half(acc[nf][0] + bb.x);
            sVs[(col + 1) * LDA1 + wr0 + g]     = __float2half(acc[nf][1] + bb.y);
            sVs[(col + 0) * LDA1 + wr0 + 8 + g] = __float2half(acc[nf][2] + bb.x);
            sVs[(col + 1) * LDA1 + wr0 + 8 + g] = __float2half(acc[nf][3] + bb.y);
        }
        __syncthreads();
#pragma unroll
        for (int i = 0; i < 8; i++) {
            int idx = tid + i * 128;
            int d = idx >> 3, k8 = idx & 7;
            uint4 v = *(const uint4*)&sVs[d * LDA1 + k8 * 8];
            *(uint4*)&gVt[(size_t)d * N_E + r0 + k8 * 8] = v;
        }
    } else {
        __half* dst = (which == 0) ? gQh : gKh;
#pragma unroll
        for (int nf = 0; nf < 16; nf++) {
            int col = nf * 8 + 2 * tig;
            float2 bb = *(const float2*)&b[col];
            __half2 h0 = __floats2half2_rn((acc[nf][0] + bb.x) * oscale,
                                           (acc[nf][1] + bb.y) * oscale);
            __half2 h1 = __floats2half2_rn((acc[nf][2] + bb.x) * oscale,
                                           (acc[nf][3] + bb.y) * oscale);
            *(uint32_t*)&dst[(size_t)(r0 + wr0 + g) * D + col]     = *(uint32_t*)&h0;
            *(uint32_t*)&dst[(size_t)(r0 + wr0 + 8 + g) * D + col] = *(uint32_t*)&h1;
        }
    }
}

// ==================== K2: attention — software-pipelined S/PV ================
// Iter jt runs PV(jt) and S(jt+1) in ONE barrier-free region (disjoint smem).
// P carried across barrier 2 in registers; sP holds P(jt) during phase M.
__global__ __launch_bounds__(NTHR, 1) void attn_kernel(
    const int* __restrict__ mask, float* __restrict__ attn, float* __restrict__ out0)
{
    if (out0 == nullptr) out0 = gOscratch;

    extern __shared__ char sm[];
    uint32_t sb = smem_u32(sm);
    float* sRow = (float*)(sm + ROWOFF);
    float* sInv = (float*)(sm + INVOFF);

    int tid  = threadIdx.x;
    int lane = tid & 31, wid = tid >> 5;
    int g = lane >> 2, tig = lane & 3;
    int wm = wid >> 2, wn = wid & 3;       // 4 m-groups x 4 n-groups
    int i0 = blockIdx.x * BM;

    if (tid < 64) sRow[tid] = 0.f;

    int mrow = wm * 16 + g;
    int ncol0 = wn * 32;

    // ---- Q tile (64 x 128 halves) ----
#pragma unroll
    for (int k = 0; k < 2; k++) {
        int t = tid + k * NTHR;
        int r = t >> 4, cc = t & 15;
        uint4 v = *(const uint4*)&gQh[(size_t)(i0 + r) * D + cc * 8];
        *(uint4*)(sm + QOFF + r * LDB + cc * 16) = v;
    }

    const uint32_t kbuf[2] = { sb + KOFF0, sb + KOFF1 };
    const uint32_t vbuf[2] = { sb + VOFF0, sb + VOFF1 };
    // prologue prefetch: {K0, V0}, then {K1}
#pragma unroll
    for (int k = 0; k < 4; k++) {
        int c = tid + k * NTHR;
        int row = c >> 4, cc = c & 15;
        cpa16(kbuf[0] + row * LDB + cc * 16, &gKh[(size_t)row * D + cc * 8]);
        cpa16(vbuf[0] + row * LDB + cc * 16, &gVt[(size_t)row * N_E + cc * 8]);
    }
    CP_COMMIT();
#pragma unroll
    for (int k = 0; k < 4; k++) {
        int c = tid + k * NTHR;
        int row = c >> 4, cc = c & 15;
        cpa16(kbuf[1] + row * LDB + cc * 16, &gKh[(size_t)(BN + row) * D + cc * 8]);
    }
    CP_COMMIT();

    float oAcc[4][4];
#pragma unroll
    for (int ni = 0; ni < 4; ni++)
#pragma unroll
        for (int c = 0; c < 4; c++) oAcc[ni][c] = 0.f;
    float rs0 = 0.f, rs1 = 0.f;

    // ================= prologue: compute P(0) into sP =================
    CP_WAIT0();
    __syncthreads();                       // Q, K0, V0 resident
    {
        int2 mreg[4][2];
#pragma unroll
        for (int ni = 0; ni < 4; ni++) {
            size_t gr0 = (size_t)(i0 + mrow) * N_E + ncol0 + ni * 8 + 2 * tig;
            mreg[ni][0] = *(const int2*)&mask[gr0];
            mreg[ni][1] = *(const int2*)&mask[gr0 + 8 * N_E];
        }
        float sAcc[4][4];
#pragma unroll
        for (int ni = 0; ni < 4; ni++)
#pragma unroll
            for (int c = 0; c < 4; c++) sAcc[ni][c] = 0.f;
#pragma unroll
        for (int ks = 0; ks < 8; ks++) {
            int kb = (ks * 16 + 2 * tig) * 2;
            uint32_t ro = (uint32_t)mrow * LDB;
            uint32_t a0 = *(const uint32_t*)(sm + QOFF + ro + kb);
            uint32_t a1 = *(const uint32_t*)(sm + QOFF + ro + 8 * LDB + kb);
            uint32_t a2 = *(const uint32_t*)(sm + QOFF + ro + kb + 16);
            uint32_t a3 = *(const uint32_t*)(sm + QOFF + ro + 8 * LDB + kb + 16);
#pragma unroll
            for (int ni = 0; ni < 4; ni++) {
                uint32_t rb = (uint32_t)(ncol0 + ni * 8 + g) * LDB;
                uint32_t b0 = *(const uint32_t*)((char*)sm + KOFF0 + rb + kb);
                uint32_t b1 = *(const uint32_t*)((char*)sm + KOFF0 + rb + kb + 16);
                mma16(sAcc[ni], a0, a1, a2, a3, b0, b1);
            }
        }
#pragma unroll
        for (int ni = 0; ni < 4; ni++) {
            int lc = ncol0 + ni * 8 + 2 * tig;
            float p0 = mreg[ni][0].x ? __expf(sAcc[ni][0]) : 0.f;
            float p1 = mreg[ni][0].y ? __expf(sAcc[ni][1]) : 0.f;
            float p2 = mreg[ni][1].x ? __expf(sAcc[ni][2]) : 0.f;
            float p3 = mreg[ni][1].y ? __expf(sAcc[ni][3]) : 0.f;
            rs0 += p0 + p1;
            rs1 += p2 + p3;
            __half2 h0 = __floats2half2_rn(p0, p1);
            __half2 h1 = __floats2half2_rn(p2, p3);
            *(uint32_t*)(sm + POFF + mrow * LDB + lc * 2)       = *(uint32_t*)&h0;
            *(uint32_t*)(sm + POFF + (mrow + 8) * LDB + lc * 2) = *(uint32_t*)&h1;
        }
    }

    // ================= main pipelined loop =================
    for (int jt = 0; jt < NT; jt++) {
        int haveS = (jt + 1 < NT);
        uint32_t sV = vbuf[jt & 1];
        uint32_t sK = kbuf[(jt + 1) & 1];

        CP_WAIT0();                        // group from iter jt-1 resident
        __syncthreads();                   // barrier 1: sP(jt) visible, buffers safe

        // ---- prefetch K(jt+2), V(jt+1) (targets' readers finished last iter) ----
        if (jt + 2 < NT) {
            int jn = (jt + 2) * BN;
            uint32_t kb2 = kbuf[jt & 1];
#pragma unroll
            for (int k = 0; k < 4; k++) {
                int c = tid + k * NTHR;
                int row = c >> 4, cc = c & 15;
                cpa16(kb2 + row * LDB + cc * 16, &gKh[(size_t)(jn + row) * D + cc * 8]);
            }
        }
        if (haveS) {
            int jn = (jt + 1) * BN;
            uint32_t vb2 = vbuf[(jt + 1) & 1];
#pragma unroll
            for (int k = 0; k < 4; k++) {
                int c = tid + k * NTHR;
                int row = c >> 4, cc = c & 15;
                cpa16(vb2 + row * LDB + cc * 16, &gVt[(size_t)row * N_E + jn + cc * 8]);
            }
        }
        CP_COMMIT();

        // ---- mask prefetch for tile jt+1 ----
        int2 mreg[4][2];
        if (haveS) {
            size_t jn = (size_t)(jt + 1) * BN;
#pragma unroll
            for (int ni = 0; ni < 4; ni++) {
                size_t gr0 = (size_t)(i0 + mrow) * N_E + jn + ncol0 + ni * 8 + 2 * tig;
                mreg[ni][0] = *(const int2*)&mask[gr0];
                mreg[ni][1] = *(const int2*)&mask[gr0 + 8 * N_E];
            }
        }

        // ---- PHASE M: S(jt+1) + PV(jt) + P(jt) copy — one barrier-free region ----
        float sAcc[4][4];
#pragma unroll
        for (int ni = 0; ni < 4; ni++)
#pragma unroll
            for (int c = 0; c < 4; c++) sAcc[ni][c] = 0.f;

        if (haveS) {
#pragma unroll
            for (int ks = 0; ks < 8; ks++) {
                int kb = (ks * 16 + 2 * tig) * 2;
                uint32_t ro = (uint32_t)mrow * LDB;
                uint32_t a0 = *(const uint32_t*)(sm + QOFF + ro + kb);
                uint32_t a1 = *(const uint32_t*)(sm + QOFF + ro + 8 * LDB + kb);
                uint32_t a2 = *(const uint32_t*)(sm + QOFF + ro + kb + 16);
                uint32_t a3 = *(const uint32_t*)(sm + QOFF + ro + 8 * LDB + kb + 16);
#pragma unroll
                for (int ni = 0; ni < 4; ni++) {
                    uint32_t rb = (uint32_t)(ncol0 + ni * 8 + g) * LDB;
                    uint32_t b0 = *(const uint32_t*)((char*)sm + (sK - sb) + rb + kb);
                    uint32_t b1 = *(const uint32_t*)((char*)sm + (sK - sb) + rb + kb + 16);
                    mma16(sAcc[ni], a0, a1, a2, a3, b0, b1);
                }
            }
        }

#pragma unroll
        for (int ks = 0; ks < 8; ks++) {
            int kb = (ks * 16 + 2 * tig) * 2;
            uint32_t ro = (uint32_t)mrow * LDB;
            uint32_t a0 = *(const uint32_t*)(sm + POFF + ro + kb);
            uint32_t a1 = *(const uint32_t*)(sm + POFF + ro + 8 * LDB + kb);
            uint32_t a2 = *(const uint32_t*)(sm + POFF + ro + kb + 16);
            uint32_t a3 = *(const uint32_t*)(sm + POFF + ro + 8 * LDB + kb + 16);
#pragma unroll
            for (int ni = 0; ni < 4; ni++) {
                uint32_t rb = (uint32_t)(ncol0 + ni * 8 + g) * LDB;
                uint32_t b0 = *(const uint32_t*)((char*)sm + (sV - sb) + rb + kb);
                uint32_t b1 = *(const uint32_t*)((char*)sm + (sV - sb) + rb + kb + 16);
                mma16(oAcc[ni], a0, a1, a2, a3, b0, b1);
            }
        }

        // coalesced sP (= P(jt)) -> gPstage
        {
            int j0 = jt * BN;
#pragma unroll
            for (int k = 0; k < 2; k++) {
                int t = tid + k * NTHR;
                int r = t >> 4, cc = t & 15;
                uint4 v = *(const uint4*)(sm + POFF + r * LDB + cc * 16);
                *(uint4*)&gPstage[(size_t)(i0 + r) * N_E + j0 + cc * 8] = v;
            }
        }

        // ---- epilogue(jt+1): exp -> packed registers ----
        uint32_t ph[8];
        if (haveS) {
#pragma unroll
            for (int ni = 0; ni < 4; ni++) {
                float p0 = mreg[ni][0].x ? __expf(sAcc[ni][0]) : 0.f;
                float p1 = mreg[ni][0].y ? __expf(sAcc[ni][1]) : 0.f;
                float p2 = mreg[ni][1].x ? __expf(sAcc[ni][2]) : 0.f;
                float p3 = mreg[ni][1].y ? __expf(sAcc[ni][3]) : 0.f;
                rs0 += p0 + p1;
                rs1 += p2 + p3;
                __half2 h0 = __floats2half2_rn(p0, p1);
                __half2 h1 = __floats2half2_rn(p2, p3);
                ph[ni * 2]     = *(uint32_t*)&h0;
                ph[ni * 2 + 1] = *(uint32_t*)&h1;
            }
        }

        __syncthreads();                   // barrier 2: PV(jt) done reading sP

        if (haveS) {
#pragma unroll
            for (int ni = 0; ni < 4; ni++) {
                int lc = ncol0 + ni * 8 + 2 * tig;
                *(uint32_t*)(sm + POFF + mrow * LDB + lc * 2)       = ph[ni * 2];
                *(uint32_t*)(sm + POFF + (mrow + 8) * LDB + lc * 2) = ph[ni * 2 + 1];
            }
        }
    }

    // ---- rowsum reduce -> inv ----
    {
        float v0 = rs0, v1 = rs1;
        v0 += __shfl_xor_sync(0xffffffffu, v0, 1);
        v0 += __shfl_xor_sync(0xffffffffu, v0, 2);
        v1 += __shfl_xor_sync(0xffffffffu, v1, 1);
        v1 += __shfl_xor_sync(0xffffffffu, v1, 2);
        if (tig == 0) {
            atomicAdd(&sRow[wm * 16 + g], v0);
            atomicAdd(&sRow[wm * 16 + 8 + g], v1);
        }
    }
    __syncthreads();
    if (tid < 64) sInv[tid] = 1.0f / sRow[tid];
    __syncthreads();

    // ---- write normalized O ----
    {
        float iv0 = sInv[mrow], iv1 = sInv[mrow + 8];
#pragma unroll
        for (int ni = 0; ni < 4; ni++) {
            int c = ncol0 + ni * 8 + 2 * tig;
            *(float2*)&out0[(size_t)(i0 + mrow) * D + c] =
                make_float2(oAcc[ni][0] * iv0, oAcc[ni][1] * iv0);
            *(float2*)&out0[(size_t)(i0 + mrow + 8) * D + c] =
                make_float2(oAcc[ni][2] * iv1, oAcc[ni][3] * iv1);
        }
    }

    // ---- fused normalization: fp16 stage -> fp32 attn, fully coalesced ----
    const __half* pst = gPstage + (size_t)i0 * N_E;
    float4* a4 = (float4*)(attn + (size_t)i0 * N_E);
    const int totalc = 64 * (N_E / 4);     // 131072 uint2 chunks
    for (int base = 0; base < totalc; base += NTHR * 8) {
        uint2 v[8];
        int idx[8];
#pragma unroll
        for (int u = 0; u < 8; u++) {
            idx[u] = base + u * NTHR + tid;
            v[u] = *(const uint2*)&pst[(size_t)idx[u] * 4];
        }
#pragma unroll
        for (int u = 0; u < 8; u++) {
            float inv = sInv[idx[u] >> 11];
            const __half2* h2 = (const __half2*)&v[u];
            float2 f0 = __half22float2(h2[0]);
            float2 f1 = __half22float2(h2[1]);
            a4[idx[u]] = make_float4(f0.x * inv, f0.y * inv, f1.x * inv, f1.y * inv);
        }
    }
}

// ==================== host ====================
extern "C" void kernel_launch(void* const* d_in, const int* in_sizes, int n_in,
                              void* d_out, int out_size)
{
    const float* embC = (const float*)d_in[0];
    const float* embE = (const float*)d_in[1];
    const int*   mask = (const int*)d_in[2];
    const float* Wq = (const float*)d_in[3];
    const float* bq = (const float*)d_in[4];
    const float* Wk = (const float*)d_in[5];
    const float* bk = (const float*)d_in[6];
    const float* Wv = (const float*)d_in[7];
    const float* bv = (const float*)d_in[8];

    float* base = (float*)d_out;
    long long t2 = (long long)N_C * N_E;

    float* out0;
    float* attn;
    if ((long long)out_size == t2) {
        out0 = nullptr;
        attn = base;
    } else {
        out0 = base;
        attn = base + (long long)N_C * D;
    }

    dim3 pgrid(N_C / 64, 3);
    proj_kernel<<<pgrid, 128>>>(embC, embE, Wq, bq, Wk, bk, Wv, bv);

    static int configured = 0;
    if (!configured) {
        cudaFuncSetAttribute(attn_kernel, cudaFuncAttributeMaxDynamicSharedMemorySize, SMEM_TOTAL);
        configured = 1;
    }
    attn_kernel<<<N_C / BM, NTHR, SMEM_TOTAL>>>(mask, attn, out0);
}